// round 1
// baseline (speedup 1.0000x reference)
#include <cuda_runtime.h>
#include <math.h>

#define N_NODES 50000
#define BATCH   512
#define F0      78
#define NH1     10
#define D1      780
#define C2      128
#define EMBD    128
#define SEQ     1000
#define VOCAB   26
#define KW      8
#define NF      32
#define LOUT    121
#define E_TOT   250000

// ---------------- scratch (device globals; no allocations) ----------------
__device__ float g_h1 [N_NODES * D1];     // x @ W1
__device__ float g_h1e[N_NODES * D1];     // elu(agg1 + b1)
__device__ float g_h2 [N_NODES * C2];     // h1e @ W2
__device__ float g_o2 [N_NODES * C2];     // relu(agg2 + b2)
__device__ float g_als1[N_NODES * NH1];
__device__ float g_ald1[N_NODES * NH1];
__device__ float g_als2[N_NODES];
__device__ float g_ald2[N_NODES];
__device__ int   g_deg [N_NODES];
__device__ int   g_off [N_NODES + 1];
__device__ int   g_cur [N_NODES];
__device__ int   g_srcs[E_TOT];
__device__ int   g_starts[BATCH + 1];
__device__ float g_A   [BATCH * NF * VOCAB * KW];  // 512*32*208
__device__ float g_Ek  [VOCAB * KW * LOUT];        // 208*121
__device__ float g_conv[BATCH * NF * LOUT];        // 16384*121
__device__ float g_pool[BATCH * C2];
__device__ float g_xc  [BATCH * 2 * C2];
__device__ float g_f1  [BATCH * 1024];
__device__ float g_f2  [BATCH * 256];

// ---------------- CSR build ----------------
__global__ void deg_init_k(int* deg) {
    int i = blockIdx.x * blockDim.x + threadIdx.x;
    if (i < N_NODES) deg[i] = 1;  // self loop
}
__global__ void hist_k(const int* __restrict__ ei, int* deg, int E) {
    int e = blockIdx.x * blockDim.x + threadIdx.x;
    if (e < E) atomicAdd(&deg[ei[E + e]], 1);
}
__global__ void scan_k(const int* __restrict__ deg, int* off, int n) {
    __shared__ int tmp[1024];
    __shared__ int carry;
    int tid = threadIdx.x;
    if (tid == 0) { carry = 0; off[0] = 0; }
    __syncthreads();
    for (int base = 0; base < n; base += 1024) {
        int v = (base + tid < n) ? deg[base + tid] : 0;
        tmp[tid] = v;
        __syncthreads();
        for (int s = 1; s < 1024; s <<= 1) {
            int a = (tid >= s) ? tmp[tid - s] : 0;
            __syncthreads();
            tmp[tid] += a;
            __syncthreads();
        }
        if (base + tid < n) off[base + tid + 1] = carry + tmp[tid];
        __syncthreads();
        if (tid == 0) carry += tmp[1023];
        __syncthreads();
    }
}
__global__ void selfloop_k(const int* __restrict__ off, int* cur, int* srcs) {
    int i = blockIdx.x * blockDim.x + threadIdx.x;
    if (i < N_NODES) { int b = off[i]; srcs[b] = i; cur[i] = b + 1; }
}
__global__ void fill_k(const int* __restrict__ ei, int* cur, int* srcs, int E) {
    int e = blockIdx.x * blockDim.x + threadIdx.x;
    if (e < E) {
        int d = ei[E + e];
        int p = atomicAdd(&cur[d], 1);
        srcs[p] = ei[e];
    }
}

// ---------------- generic tiled GEMM (64x64 tile, 256 thr, 4x4/thr) ----------------
template <bool BIAS, bool RELU, bool ATOMIC>
__global__ void gemm_k(int M, int N, int K,
                       const float* __restrict__ A, int lda,
                       const float* __restrict__ B, int ldb,
                       float* __restrict__ C, int ldc,
                       const float* __restrict__ bias, int kchunk) {
    __shared__ float As[16][68];
    __shared__ float Bs[16][68];
    int tid = threadIdx.x;
    int tx = tid & 15, ty = tid >> 4;
    int row0 = blockIdx.y * 64, col0 = blockIdx.x * 64;
    int kbeg = blockIdx.z * kchunk;
    int kend = min(K, kbeg + kchunk);
    float acc[4][4] = {};
    int ar = tid >> 2;          // 0..63
    int ak = (tid & 3) * 4;     // 0,4,8,12
    int br = tid >> 4;          // 0..15
    int bc = (tid & 15) * 4;    // 0..60
    for (int k0 = kbeg; k0 < kend; k0 += 16) {
#pragma unroll
        for (int j = 0; j < 4; j++) {
            int kk = k0 + ak + j;
            As[ak + j][ar] = (row0 + ar < M && kk < kend)
                ? A[(long)(row0 + ar) * lda + kk] : 0.f;
        }
#pragma unroll
        for (int j = 0; j < 4; j++) {
            int kk = k0 + br;
            Bs[br][bc + j] = (kk < kend && col0 + bc + j < N)
                ? B[(long)kk * ldb + col0 + bc + j] : 0.f;
        }
        __syncthreads();
#pragma unroll
        for (int kk = 0; kk < 16; kk++) {
            float4 av = *reinterpret_cast<const float4*>(&As[kk][ty * 4]);
            float4 bv = *reinterpret_cast<const float4*>(&Bs[kk][tx * 4]);
            float a[4] = {av.x, av.y, av.z, av.w};
            float b[4] = {bv.x, bv.y, bv.z, bv.w};
#pragma unroll
            for (int i = 0; i < 4; i++)
#pragma unroll
                for (int j = 0; j < 4; j++) acc[i][j] += a[i] * b[j];
        }
        __syncthreads();
    }
#pragma unroll
    for (int i = 0; i < 4; i++) {
        int r = row0 + ty * 4 + i;
        if (r >= M) continue;
#pragma unroll
        for (int j = 0; j < 4; j++) {
            int c = col0 + tx * 4 + j;
            if (c >= N) continue;
            float v = acc[i][j];
            if (ATOMIC) {
                atomicAdd(&C[(long)r * ldc + c], v);
            } else {
                if (BIAS) v += bias[c];
                if (RELU) v = fmaxf(v, 0.f);
                C[(long)r * ldc + c] = v;
            }
        }
    }
}

__global__ void bias_init_k(float* C, int ldc, int M, int N, const float* __restrict__ bias) {
    int idx = blockIdx.x * blockDim.x + threadIdx.x;
    if (idx < M * N) { int r = idx / N, c = idx % N; C[(long)r * ldc + c] = bias[c]; }
}
__global__ void relu_ip_k(float* C, int ldc, int M, int N) {
    int idx = blockIdx.x * blockDim.x + threadIdx.x;
    if (idx < M * N) { int r = idx / N, c = idx % N; C[(long)r * ldc + c] = fmaxf(C[(long)r * ldc + c], 0.f); }
}

// ---------------- attention logit params ----------------
__global__ void attn1_k(const float* __restrict__ h1, const float* __restrict__ asr,
                        const float* __restrict__ adt, float* als, float* ald) {
    int t = blockIdx.x * blockDim.x + threadIdx.x;
    if (t >= N_NODES * NH1) return;
    int i = t / NH1, h = t - i * NH1;
    const float* hr = h1 + (long)i * D1 + h * F0;
    float s = 0.f, d = 0.f;
#pragma unroll 6
    for (int c = 0; c < F0; c++) {
        float v = hr[c];
        s += v * asr[h * F0 + c];
        d += v * adt[h * F0 + c];
    }
    als[t] = s; ald[t] = d;
}
__global__ void attn2_k(const float* __restrict__ h2, const float* __restrict__ asr,
                        const float* __restrict__ adt, float* als, float* ald) {
    int i = blockIdx.x * blockDim.x + threadIdx.x;
    if (i >= N_NODES) return;
    const float* hr = h2 + (long)i * C2;
    float s = 0.f, d = 0.f;
#pragma unroll 8
    for (int c = 0; c < C2; c++) {
        float v = hr[c];
        s += v * asr[c];
        d += v * adt[c];
    }
    als[i] = s; ald[i] = d;
}

// ---------------- GAT layer 1 aggregation: softmax over incoming edges + scatter ----------------
#define CH1 32
__global__ void agg1_k(const float* __restrict__ h1, const float* __restrict__ als,
                       const float* __restrict__ ald, const int* __restrict__ off,
                       const int* __restrict__ srcs, const float* __restrict__ b1,
                       float* __restrict__ out) {
    int i = blockIdx.x, tid = threadIdx.x;  // 256 threads
    __shared__ float aldi[NH1], m[NH1], ssum[NH1], sinv[NH1];
    __shared__ float w[CH1][NH1];
    __shared__ int ssrc[CH1];
    int base = off[i];
    int deg = off[i + 1] - base;
    if (tid < NH1) { aldi[tid] = ald[i * NH1 + tid]; m[tid] = -1e30f; ssum[tid] = 0.f; }
    __syncthreads();
    // pass 1: per-head max
    for (int c0 = 0; c0 < deg; c0 += CH1) {
        int n = min(CH1, deg - c0);
        if (tid < n) ssrc[tid] = srcs[base + c0 + tid];
        __syncthreads();
        for (int t = tid; t < n * NH1; t += 256) {
            int e = t / NH1, hh = t - e * NH1;
            float l = als[ssrc[e] * NH1 + hh] + aldi[hh];
            w[e][hh] = l > 0.f ? l : 0.2f * l;
        }
        __syncthreads();
        if (tid < NH1) {
            float mm = m[tid];
            for (int e = 0; e < n; e++) mm = fmaxf(mm, w[e][tid]);
            m[tid] = mm;
        }
        __syncthreads();
    }
    // pass 2: per-head denom
    for (int c0 = 0; c0 < deg; c0 += CH1) {
        int n = min(CH1, deg - c0);
        if (tid < n) ssrc[tid] = srcs[base + c0 + tid];
        __syncthreads();
        for (int t = tid; t < n * NH1; t += 256) {
            int e = t / NH1, hh = t - e * NH1;
            float l = als[ssrc[e] * NH1 + hh] + aldi[hh];
            l = l > 0.f ? l : 0.2f * l;
            w[e][hh] = expf(l - m[hh]);
        }
        __syncthreads();
        if (tid < NH1) {
            float s = ssum[tid];
            for (int e = 0; e < n; e++) s += w[e][tid];
            ssum[tid] = s;
        }
        __syncthreads();
    }
    if (tid < NH1) sinv[tid] = 1.f / (ssum[tid] + 1e-16f);
    __syncthreads();
    // pass 3: weighted scatter
    float a0 = 0.f, a1 = 0.f, a2 = 0.f, a3 = 0.f;
    int h0 = tid / F0, h1i = (tid + 256) / F0, h2i = (tid + 512) / F0;
    for (int c0 = 0; c0 < deg; c0 += CH1) {
        int n = min(CH1, deg - c0);
        if (tid < n) ssrc[tid] = srcs[base + c0 + tid];
        __syncthreads();
        for (int t = tid; t < n * NH1; t += 256) {
            int e = t / NH1, hh = t - e * NH1;
            float l = als[ssrc[e] * NH1 + hh] + aldi[hh];
            l = l > 0.f ? l : 0.2f * l;
            w[e][hh] = expf(l - m[hh]) * sinv[hh];
        }
        __syncthreads();
        for (int e = 0; e < n; e++) {
            const float* hr = h1 + (long)ssrc[e] * D1;
            a0 += w[e][h0]  * hr[tid];
            a1 += w[e][h1i] * hr[tid + 256];
            a2 += w[e][h2i] * hr[tid + 512];
            if (tid < D1 - 768) a3 += w[e][NH1 - 1] * hr[tid + 768];
        }
        __syncthreads();
    }
    {
        float v = a0 + b1[tid];
        out[(long)i * D1 + tid] = v > 0.f ? v : expf(v) - 1.f;
    }
    {
        float v = a1 + b1[tid + 256];
        out[(long)i * D1 + tid + 256] = v > 0.f ? v : expf(v) - 1.f;
    }
    {
        float v = a2 + b1[tid + 512];
        out[(long)i * D1 + tid + 512] = v > 0.f ? v : expf(v) - 1.f;
    }
    if (tid < D1 - 768) {
        float v = a3 + b1[tid + 768];
        out[(long)i * D1 + tid + 768] = v > 0.f ? v : expf(v) - 1.f;
    }
}

// ---------------- GAT layer 2 aggregation (1 head, 128 ch) ----------------
#define CH2 64
__global__ void agg2_k(const float* __restrict__ h2, const float* __restrict__ als,
                       const float* __restrict__ ald, const int* __restrict__ off,
                       const int* __restrict__ srcs, const float* __restrict__ b2,
                       float* __restrict__ out) {
    int i = blockIdx.x, tid = threadIdx.x;  // 128 threads
    __shared__ float w[CH2];
    __shared__ int ssrc[CH2];
    __shared__ float sm, ss, sinv, aldi;
    if (tid == 0) { aldi = ald[i]; sm = -1e30f; ss = 0.f; }
    int base = off[i];
    int deg = off[i + 1] - base;
    __syncthreads();
    for (int c0 = 0; c0 < deg; c0 += CH2) {
        int n = min(CH2, deg - c0);
        if (tid < n) {
            int s_ = srcs[base + c0 + tid];
            ssrc[tid] = s_;
            float l = als[s_] + aldi;
            w[tid] = l > 0.f ? l : 0.2f * l;
        }
        __syncthreads();
        if (tid == 0) {
            float mm = sm;
            for (int e = 0; e < n; e++) mm = fmaxf(mm, w[e]);
            sm = mm;
        }
        __syncthreads();
    }
    for (int c0 = 0; c0 < deg; c0 += CH2) {
        int n = min(CH2, deg - c0);
        if (tid < n) {
            int s_ = srcs[base + c0 + tid];
            float l = als[s_] + aldi;
            l = l > 0.f ? l : 0.2f * l;
            w[tid] = expf(l - sm);
        }
        __syncthreads();
        if (tid == 0) {
            float s = ss;
            for (int e = 0; e < n; e++) s += w[e];
            ss = s;
        }
        __syncthreads();
    }
    if (tid == 0) sinv = 1.f / (ss + 1e-16f);
    __syncthreads();
    float acc = 0.f;
    for (int c0 = 0; c0 < deg; c0 += CH2) {
        int n = min(CH2, deg - c0);
        if (tid < n) {
            int s_ = srcs[base + c0 + tid];
            ssrc[tid] = s_;
            float l = als[s_] + aldi;
            l = l > 0.f ? l : 0.2f * l;
            w[tid] = expf(l - sm) * sinv;
        }
        __syncthreads();
        for (int e = 0; e < n; e++)
            acc += w[e] * h2[(long)ssrc[e] * C2 + tid];
        __syncthreads();
    }
    float v = acc + b2[tid];
    out[(long)i * C2 + tid] = fmaxf(v, 0.f);
}

// ---------------- pooling ----------------
__global__ void starts_k(const int* __restrict__ batch, int* starts) {
    int i = blockIdx.x * blockDim.x + threadIdx.x;
    if (i >= N_NODES) return;
    if (i == 0) starts[0] = 0;
    else if (batch[i] != batch[i - 1]) starts[batch[i]] = i;
    if (i == N_NODES - 1) starts[BATCH] = N_NODES;
}
__global__ void pool_k(const float* __restrict__ o2, const int* __restrict__ starts,
                       float* __restrict__ g) {
    int b = blockIdx.x, c = threadIdx.x;  // 128 threads
    int s = starts[b], e = starts[b + 1];
    float m = -1e30f;
    for (int r = s; r < e; r++) m = fmaxf(m, o2[(long)r * C2 + c]);
    g[b * C2 + c] = m;
}

// ---------------- conv branch: scatter conv_w by token-id ----------------
__global__ void scatterA_k(const int* __restrict__ target, const float* __restrict__ cw,
                           float* __restrict__ A) {
    int b = blockIdx.x, tid = threadIdx.x;  // 256 threads = (o,k)
    __shared__ float Ash[NF * VOCAB * KW];  // 6656 floats
    for (int i = tid; i < NF * VOCAB * KW; i += 256) Ash[i] = 0.f;
    __syncthreads();
    int o = tid >> 3, k = tid & 7;
    const float* wrow = cw + o * (SEQ * KW) + k;
    float* arow = Ash + o * (VOCAB * KW) + k;
    for (int s = 0; s < SEQ; s++) {
        int v = target[b * SEQ + s];
        arow[v * KW] += wrow[s * KW];
    }
    __syncthreads();
    for (int i = tid; i < NF * VOCAB * KW; i += 256)
        A[(long)b * (NF * VOCAB * KW) + i] = Ash[i];
}
__global__ void ek_k(const float* __restrict__ emb, float* __restrict__ Ek) {
    int idx = blockIdx.x * blockDim.x + threadIdx.x;
    if (idx >= VOCAB * KW * LOUT) return;
    int vk = idx / LOUT, l = idx - vk * LOUT;
    Ek[idx] = emb[(vk >> 3) * EMBD + (vk & 7) + l];
}
__global__ void conv_epi_k(float* __restrict__ c, const float* __restrict__ cb) {
    int idx = blockIdx.x * blockDim.x + threadIdx.x;
    if (idx >= BATCH * NF * LOUT) return;
    int o = (idx / LOUT) & (NF - 1);
    c[idx] = fmaxf(c[idx] + cb[o], 0.f);
}

// ---------------- final ----------------
__global__ void final_k(const float* __restrict__ x, const float* __restrict__ w,
                        const float* __restrict__ b, float* __restrict__ y) {
    int gw = (blockIdx.x * blockDim.x + threadIdx.x) >> 5;
    int lane = threadIdx.x & 31;
    if (gw >= BATCH) return;
    float s = 0.f;
#pragma unroll
    for (int j = lane; j < 256; j += 32) s += x[gw * 256 + j] * w[j];
#pragma unroll
    for (int o = 16; o; o >>= 1) s += __shfl_down_sync(0xffffffffu, s, o);
    if (lane == 0) y[gw] = s + b[0];
}

// ---------------- host ----------------
extern "C" void kernel_launch(void* const* d_in, const int* in_sizes, int n_in,
                              void* d_out, int out_size) {
    const float* x       = (const float*)d_in[0];
    const int*   ei      = (const int*)d_in[1];
    const int*   batch   = (const int*)d_in[2];
    const int*   target  = (const int*)d_in[3];
    const float* W1      = (const float*)d_in[4];
    const float* a_src1  = (const float*)d_in[5];
    const float* a_dst1  = (const float*)d_in[6];
    const float* b1      = (const float*)d_in[7];
    const float* W2      = (const float*)d_in[8];
    const float* a_src2  = (const float*)d_in[9];
    const float* a_dst2  = (const float*)d_in[10];
    const float* b2      = (const float*)d_in[11];
    const float* fc_g1_w = (const float*)d_in[12];
    const float* fc_g1_b = (const float*)d_in[13];
    const float* emb     = (const float*)d_in[14];
    const float* conv_w  = (const float*)d_in[15];
    const float* conv_b  = (const float*)d_in[16];
    const float* fc_xt_w = (const float*)d_in[17];
    const float* fc_xt_b = (const float*)d_in[18];
    const float* fc1_w   = (const float*)d_in[19];
    const float* fc1_b   = (const float*)d_in[20];
    const float* fc2_w   = (const float*)d_in[21];
    const float* fc2_b   = (const float*)d_in[22];
    const float* out_w   = (const float*)d_in[23];
    const float* out_b   = (const float*)d_in[24];
    float* y = (float*)d_out;
    int E = in_sizes[1] / 2;

    float *h1p, *h1ep, *h2p, *o2p, *als1p, *ald1p, *als2p, *ald2p;
    float *Ap, *Ekp, *convp, *poolp, *xcp, *f1p, *f2p;
    int *degp, *offp, *curp, *srcsp, *startsp;
    cudaGetSymbolAddress((void**)&h1p, g_h1);
    cudaGetSymbolAddress((void**)&h1ep, g_h1e);
    cudaGetSymbolAddress((void**)&h2p, g_h2);
    cudaGetSymbolAddress((void**)&o2p, g_o2);
    cudaGetSymbolAddress((void**)&als1p, g_als1);
    cudaGetSymbolAddress((void**)&ald1p, g_ald1);
    cudaGetSymbolAddress((void**)&als2p, g_als2);
    cudaGetSymbolAddress((void**)&ald2p, g_ald2);
    cudaGetSymbolAddress((void**)&degp, g_deg);
    cudaGetSymbolAddress((void**)&offp, g_off);
    cudaGetSymbolAddress((void**)&curp, g_cur);
    cudaGetSymbolAddress((void**)&srcsp, g_srcs);
    cudaGetSymbolAddress((void**)&startsp, g_starts);
    cudaGetSymbolAddress((void**)&Ap, g_A);
    cudaGetSymbolAddress((void**)&Ekp, g_Ek);
    cudaGetSymbolAddress((void**)&convp, g_conv);
    cudaGetSymbolAddress((void**)&poolp, g_pool);
    cudaGetSymbolAddress((void**)&xcp, g_xc);
    cudaGetSymbolAddress((void**)&f1p, g_f1);
    cudaGetSymbolAddress((void**)&f2p, g_f2);

    // CSR build (edges sorted by dst, self-loop first)
    deg_init_k<<<(N_NODES + 255) / 256, 256>>>(degp);
    hist_k<<<(E + 255) / 256, 256>>>(ei, degp, E);
    scan_k<<<1, 1024>>>(degp, offp, N_NODES);
    selfloop_k<<<(N_NODES + 255) / 256, 256>>>(offp, curp, srcsp);
    fill_k<<<(E + 255) / 256, 256>>>(ei, curp, srcsp, E);

    // GAT layer 1
    {
        dim3 g((D1 + 63) / 64, (N_NODES + 63) / 64);
        gemm_k<false, false, false><<<g, 256>>>(N_NODES, D1, F0, x, F0, W1, D1, h1p, D1, nullptr, F0);
    }
    attn1_k<<<(N_NODES * NH1 + 255) / 256, 256>>>(h1p, a_src1, a_dst1, als1p, ald1p);
    agg1_k<<<N_NODES, 256>>>(h1p, als1p, ald1p, offp, srcsp, b1, h1ep);

    // GAT layer 2
    {
        dim3 g((C2 + 63) / 64, (N_NODES + 63) / 64);
        gemm_k<false, false, false><<<g, 256>>>(N_NODES, C2, D1, h1ep, D1, W2, C2, h2p, C2, nullptr, D1);
    }
    attn2_k<<<(N_NODES + 255) / 256, 256>>>(h2p, a_src2, a_dst2, als2p, ald2p);
    agg2_k<<<N_NODES, 128>>>(h2p, als2p, ald2p, offp, srcsp, b2, o2p);

    // pooling + fc_g1 -> xc[:, :128]
    starts_k<<<(N_NODES + 255) / 256, 256>>>(batch, startsp);
    pool_k<<<BATCH, C2>>>(o2p, startsp, poolp);
    bias_init_k<<<(BATCH * C2 + 255) / 256, 256>>>(xcp, 2 * C2, BATCH, C2, fc_g1_b);
    {
        dim3 g(2, 8, 4);
        gemm_k<false, false, true><<<g, 256>>>(BATCH, C2, C2, poolp, C2, fc_g1_w, C2, xcp, 2 * C2, nullptr, 32);
    }
    relu_ip_k<<<(BATCH * C2 + 255) / 256, 256>>>(xcp, 2 * C2, BATCH, C2);

    // conv branch -> xc[:, 128:]
    scatterA_k<<<BATCH, 256>>>(target, conv_w, Ap);
    ek_k<<<(VOCAB * KW * LOUT + 255) / 256, 256>>>(emb, Ekp);
    {
        dim3 g((LOUT + 63) / 64, (BATCH * NF + 63) / 64);
        gemm_k<false, false, false><<<g, 256>>>(BATCH * NF, LOUT, VOCAB * KW, Ap, VOCAB * KW, Ekp, LOUT,
                                                convp, LOUT, nullptr, VOCAB * KW);
    }
    conv_epi_k<<<(BATCH * NF * LOUT + 255) / 256, 256>>>(convp, conv_b);
    bias_init_k<<<(BATCH * C2 + 255) / 256, 256>>>(xcp + C2, 2 * C2, BATCH, C2, fc_xt_b);
    {
        dim3 g(2, 8, 8);
        gemm_k<false, false, true><<<g, 256>>>(BATCH, C2, NF * LOUT, convp, NF * LOUT, fc_xt_w, C2,
                                               xcp + C2, 2 * C2, nullptr, 484);
    }

    // MLP head
    {
        dim3 g(16, 8);
        gemm_k<true, true, false><<<g, 256>>>(BATCH, 1024, 256, xcp, 256, fc1_w, 1024, f1p, 1024, fc1_b, 256);
    }
    bias_init_k<<<(BATCH * 256 + 255) / 256, 256>>>(f2p, 256, BATCH, 256, fc2_b);
    {
        dim3 g(4, 8, 4);
        gemm_k<false, false, true><<<g, 256>>>(BATCH, 256, 1024, f1p, 1024, fc2_w, 256, f2p, 256, nullptr, 256);
    }
    relu_ip_k<<<(BATCH * 256 + 255) / 256, 256>>>(f2p, 256, BATCH, 256);
    final_k<<<64, 256>>>(f2p, out_w, out_b, y);
}

// round 2
// speedup vs baseline: 1.2624x; 1.2624x over previous
#include <cuda_runtime.h>
#include <math.h>

#define N_NODES 50000
#define BATCH   512
#define F0      78
#define NH1     10
#define D1      780
#define C2      128
#define EMBD    128
#define SEQ     1000
#define VOCAB   26
#define KW      8
#define NF      32
#define LOUT    121
#define E_TOT   250000

// ---------------- scratch (device globals; no allocations) ----------------
__device__ float g_h1 [N_NODES * D1];
__device__ float g_h1e[N_NODES * D1];
__device__ float g_h2 [N_NODES * C2];
__device__ float g_o2 [N_NODES * C2];
__device__ float g_als1[N_NODES * NH1];
__device__ float g_ald1[N_NODES * NH1];
__device__ float g_als2[N_NODES];
__device__ float g_ald2[N_NODES];
__device__ int   g_deg [N_NODES];
__device__ int   g_off [N_NODES + 1];
__device__ int   g_cur [N_NODES];
__device__ int   g_srcs[E_TOT];
__device__ int   g_starts[BATCH + 1];
__device__ float g_A   [BATCH * NF * VOCAB * KW];
__device__ float g_Ek  [VOCAB * KW * LOUT];
__device__ float g_conv[BATCH * NF * LOUT];
__device__ float g_pool[BATCH * C2];
__device__ float g_xc  [BATCH * 2 * C2];
__device__ float g_f1  [BATCH * 1024];
__device__ float g_f2  [BATCH * 256];

// ---------------- CSR build ----------------
__global__ void deg_init_k(int* deg) {
    int i = blockIdx.x * blockDim.x + threadIdx.x;
    if (i < N_NODES) deg[i] = 1;
}
__global__ void hist_k(const int* __restrict__ ei, int* deg, int E) {
    int e = blockIdx.x * blockDim.x + threadIdx.x;
    if (e < E) atomicAdd(&deg[ei[E + e]], 1);
}
__global__ void scan_k(const int* __restrict__ deg, int* off, int n) {
    __shared__ int tmp[1024];
    __shared__ int carry;
    int tid = threadIdx.x;
    if (tid == 0) { carry = 0; off[0] = 0; }
    __syncthreads();
    for (int base = 0; base < n; base += 1024) {
        int v = (base + tid < n) ? deg[base + tid] : 0;
        tmp[tid] = v;
        __syncthreads();
        for (int s = 1; s < 1024; s <<= 1) {
            int a = (tid >= s) ? tmp[tid - s] : 0;
            __syncthreads();
            tmp[tid] += a;
            __syncthreads();
        }
        if (base + tid < n) off[base + tid + 1] = carry + tmp[tid];
        __syncthreads();
        if (tid == 0) carry += tmp[1023];
        __syncthreads();
    }
}
__global__ void selfloop_k(const int* __restrict__ off, int* cur, int* srcs) {
    int i = blockIdx.x * blockDim.x + threadIdx.x;
    if (i < N_NODES) { int b = off[i]; srcs[b] = i; cur[i] = b + 1; }
}
__global__ void fill_k(const int* __restrict__ ei, int* cur, int* srcs, int E) {
    int e = blockIdx.x * blockDim.x + threadIdx.x;
    if (e < E) {
        int d = ei[E + e];
        int p = atomicAdd(&cur[d], 1);
        srcs[p] = ei[e];
    }
}

// ---------------- tf32 tensor-core GEMM ----------------
// 128x64 block tile, 256 threads = 8 warps in 4(M) x 2(N); 32x32 per warp
// via 2x4 mma.sync.m16n8k8 tf32 tiles. fp32 accumulation.
__device__ __forceinline__ unsigned f2tf(float f) {
    unsigned r;
    asm("cvt.rna.tf32.f32 %0, %1;" : "=r"(r) : "f"(f));
    return r;
}
__device__ __forceinline__ void mma_tf32(float* c, const unsigned* a, const unsigned* b) {
    asm volatile(
        "mma.sync.aligned.m16n8k8.row.col.f32.tf32.tf32.f32 "
        "{%0,%1,%2,%3}, {%4,%5,%6,%7}, {%8,%9}, {%0,%1,%2,%3};\n"
        : "+f"(c[0]), "+f"(c[1]), "+f"(c[2]), "+f"(c[3])
        : "r"(a[0]), "r"(a[1]), "r"(a[2]), "r"(a[3]), "r"(b[0]), "r"(b[1]));
}

template <bool BIAS, bool RELU, bool ATOMIC>
__global__ void gemm_tf32_k(int M, int N, int K,
                            const float* __restrict__ A, int lda,
                            const float* __restrict__ B, int ldb,
                            float* __restrict__ C, int ldc,
                            const float* __restrict__ bias, int kchunk) {
    __shared__ unsigned As[128][36];  // pad 4: bank-conflict-free frag loads
    __shared__ unsigned Bs[32][72];   // pad 8: bank-conflict-free frag loads
    int tid = threadIdx.x;
    int lane = tid & 31, warp = tid >> 5;
    int warp_m = warp & 3, warp_n = warp >> 2;
    int row0 = blockIdx.y * 128, col0 = blockIdx.x * 64;
    int kbeg = blockIdx.z * kchunk;
    int kend = min(K, kbeg + kchunk);

    float acc[2][4][4] = {};
    int lq = lane >> 2, lr = lane & 3;

    for (int k0 = kbeg; k0 < kend; k0 += 32) {
        // load A chunk 128x32 (coalesced: consecutive tid -> consecutive k)
#pragma unroll
        for (int i = 0; i < 16; i++) {
            int idx = i * 256 + tid;
            int r = idx >> 5, kk = idx & 31;
            float v = (row0 + r < M && k0 + kk < kend)
                ? A[(long)(row0 + r) * lda + k0 + kk] : 0.f;
            As[r][kk] = f2tf(v);
        }
        // load B chunk 32x64
#pragma unroll
        for (int i = 0; i < 8; i++) {
            int idx = i * 256 + tid;
            int kr = idx >> 6, c = idx & 63;
            float v = (k0 + kr < kend && col0 + c < N)
                ? B[(long)(k0 + kr) * ldb + col0 + c] : 0.f;
            Bs[kr][c] = f2tf(v);
        }
        __syncthreads();
#pragma unroll
        for (int ks = 0; ks < 4; ks++) {
            int kb = ks * 8;
            unsigned af[2][4], bf[4][2];
#pragma unroll
            for (int mt = 0; mt < 2; mt++) {
                int rb = (warp_m << 5) + mt * 16 + lq;
                af[mt][0] = As[rb][kb + lr];
                af[mt][1] = As[rb + 8][kb + lr];
                af[mt][2] = As[rb][kb + 4 + lr];
                af[mt][3] = As[rb + 8][kb + 4 + lr];
            }
#pragma unroll
            for (int nt = 0; nt < 4; nt++) {
                int cb = (warp_n << 5) + nt * 8 + lq;
                bf[nt][0] = Bs[kb + lr][cb];
                bf[nt][1] = Bs[kb + 4 + lr][cb];
            }
#pragma unroll
            for (int mt = 0; mt < 2; mt++)
#pragma unroll
                for (int nt = 0; nt < 4; nt++)
                    mma_tf32(acc[mt][nt], af[mt], bf[nt]);
        }
        __syncthreads();
    }
    // epilogue: c0,c1 at (row, col..col+1), c2,c3 at (row+8, col..col+1)
    int r_base = row0 + (warp_m << 5) + lq;
    int c_base = col0 + (warp_n << 5) + 2 * lr;
#pragma unroll
    for (int mt = 0; mt < 2; mt++) {
#pragma unroll
        for (int half = 0; half < 2; half++) {
            int r = r_base + mt * 16 + half * 8;
            if (r >= M) continue;
#pragma unroll
            for (int nt = 0; nt < 4; nt++) {
#pragma unroll
                for (int j = 0; j < 2; j++) {
                    int c = c_base + nt * 8 + j;
                    if (c >= N) continue;
                    float v = acc[mt][nt][half * 2 + j];
                    if (ATOMIC) {
                        atomicAdd(&C[(long)r * ldc + c], v);
                    } else {
                        if (BIAS) v += bias[c];
                        if (RELU) v = fmaxf(v, 0.f);
                        C[(long)r * ldc + c] = v;
                    }
                }
            }
        }
    }
}

__global__ void bias_init_k(float* C, int ldc, int M, int N, const float* __restrict__ bias) {
    int idx = blockIdx.x * blockDim.x + threadIdx.x;
    if (idx < M * N) { int r = idx / N, c = idx % N; C[(long)r * ldc + c] = bias[c]; }
}
__global__ void relu_ip_k(float* C, int ldc, int M, int N) {
    int idx = blockIdx.x * blockDim.x + threadIdx.x;
    if (idx < M * N) { int r = idx / N, c = idx % N; C[(long)r * ldc + c] = fmaxf(C[(long)r * ldc + c], 0.f); }
}

// ---------------- attention logit params ----------------
__global__ void attn1_k(const float* __restrict__ h1, const float* __restrict__ asr,
                        const float* __restrict__ adt, float* als, float* ald) {
    int t = blockIdx.x * blockDim.x + threadIdx.x;
    if (t >= N_NODES * NH1) return;
    int i = t / NH1, h = t - i * NH1;
    const float* hr = h1 + (long)i * D1 + h * F0;
    float s = 0.f, d = 0.f;
#pragma unroll 6
    for (int c = 0; c < F0; c++) {
        float v = hr[c];
        s += v * asr[h * F0 + c];
        d += v * adt[h * F0 + c];
    }
    als[t] = s; ald[t] = d;
}
__global__ void attn2_k(const float* __restrict__ h2, const float* __restrict__ asr,
                        const float* __restrict__ adt, float* als, float* ald) {
    int i = blockIdx.x * blockDim.x + threadIdx.x;
    if (i >= N_NODES) return;
    const float* hr = h2 + (long)i * C2;
    float s = 0.f, d = 0.f;
#pragma unroll 8
    for (int c = 0; c < C2; c++) {
        float v = hr[c];
        s += v * asr[c];
        d += v * adt[c];
    }
    als[i] = s; ald[i] = d;
}

// ---------------- GAT layer 1 aggregation ----------------
#define CH1 32
__global__ void agg1_k(const float* __restrict__ h1, const float* __restrict__ als,
                       const float* __restrict__ ald, const int* __restrict__ off,
                       const int* __restrict__ srcs, const float* __restrict__ b1,
                       float* __restrict__ out) {
    int i = blockIdx.x, tid = threadIdx.x;  // 256 threads
    __shared__ float aldi[NH1], m[NH1], ssum[NH1], sinv[NH1];
    __shared__ float w[CH1][NH1];
    __shared__ int ssrc[CH1];
    int base = off[i];
    int deg = off[i + 1] - base;
    if (tid < NH1) { aldi[tid] = ald[i * NH1 + tid]; m[tid] = -1e30f; ssum[tid] = 0.f; }
    __syncthreads();
    for (int c0 = 0; c0 < deg; c0 += CH1) {
        int n = min(CH1, deg - c0);
        if (tid < n) ssrc[tid] = srcs[base + c0 + tid];
        __syncthreads();
        for (int t = tid; t < n * NH1; t += 256) {
            int e = t / NH1, hh = t - e * NH1;
            float l = als[ssrc[e] * NH1 + hh] + aldi[hh];
            w[e][hh] = l > 0.f ? l : 0.2f * l;
        }
        __syncthreads();
        if (tid < NH1) {
            float mm = m[tid];
            for (int e = 0; e < n; e++) mm = fmaxf(mm, w[e][tid]);
            m[tid] = mm;
        }
        __syncthreads();
    }
    for (int c0 = 0; c0 < deg; c0 += CH1) {
        int n = min(CH1, deg - c0);
        if (tid < n) ssrc[tid] = srcs[base + c0 + tid];
        __syncthreads();
        for (int t = tid; t < n * NH1; t += 256) {
            int e = t / NH1, hh = t - e * NH1;
            float l = als[ssrc[e] * NH1 + hh] + aldi[hh];
            l = l > 0.f ? l : 0.2f * l;
            w[e][hh] = expf(l - m[hh]);
        }
        __syncthreads();
        if (tid < NH1) {
            float s = ssum[tid];
            for (int e = 0; e < n; e++) s += w[e][tid];
            ssum[tid] = s;
        }
        __syncthreads();
    }
    if (tid < NH1) sinv[tid] = 1.f / (ssum[tid] + 1e-16f);
    __syncthreads();
    float a0 = 0.f, a1 = 0.f, a2 = 0.f, a3 = 0.f;
    int h0 = tid / F0, h1i = (tid + 256) / F0, h2i = (tid + 512) / F0;
    for (int c0 = 0; c0 < deg; c0 += CH1) {
        int n = min(CH1, deg - c0);
        if (tid < n) ssrc[tid] = srcs[base + c0 + tid];
        __syncthreads();
        for (int t = tid; t < n * NH1; t += 256) {
            int e = t / NH1, hh = t - e * NH1;
            float l = als[ssrc[e] * NH1 + hh] + aldi[hh];
            l = l > 0.f ? l : 0.2f * l;
            w[e][hh] = expf(l - m[hh]) * sinv[hh];
        }
        __syncthreads();
        for (int e = 0; e < n; e++) {
            const float* hr = h1 + (long)ssrc[e] * D1;
            a0 += w[e][h0]  * hr[tid];
            a1 += w[e][h1i] * hr[tid + 256];
            a2 += w[e][h2i] * hr[tid + 512];
            if (tid < D1 - 768) a3 += w[e][NH1 - 1] * hr[tid + 768];
        }
        __syncthreads();
    }
    {
        float v = a0 + b1[tid];
        out[(long)i * D1 + tid] = v > 0.f ? v : expf(v) - 1.f;
    }
    {
        float v = a1 + b1[tid + 256];
        out[(long)i * D1 + tid + 256] = v > 0.f ? v : expf(v) - 1.f;
    }
    {
        float v = a2 + b1[tid + 512];
        out[(long)i * D1 + tid + 512] = v > 0.f ? v : expf(v) - 1.f;
    }
    if (tid < D1 - 768) {
        float v = a3 + b1[tid + 768];
        out[(long)i * D1 + tid + 768] = v > 0.f ? v : expf(v) - 1.f;
    }
}

// ---------------- GAT layer 2 aggregation ----------------
#define CH2 64
__global__ void agg2_k(const float* __restrict__ h2, const float* __restrict__ als,
                       const float* __restrict__ ald, const int* __restrict__ off,
                       const int* __restrict__ srcs, const float* __restrict__ b2,
                       float* __restrict__ out) {
    int i = blockIdx.x, tid = threadIdx.x;  // 128 threads
    __shared__ float w[CH2];
    __shared__ int ssrc[CH2];
    __shared__ float sm, ss, sinv, aldi;
    if (tid == 0) { aldi = ald[i]; sm = -1e30f; ss = 0.f; }
    int base = off[i];
    int deg = off[i + 1] - base;
    __syncthreads();
    for (int c0 = 0; c0 < deg; c0 += CH2) {
        int n = min(CH2, deg - c0);
        if (tid < n) {
            int s_ = srcs[base + c0 + tid];
            ssrc[tid] = s_;
            float l = als[s_] + aldi;
            w[tid] = l > 0.f ? l : 0.2f * l;
        }
        __syncthreads();
        if (tid == 0) {
            float mm = sm;
            for (int e = 0; e < n; e++) mm = fmaxf(mm, w[e]);
            sm = mm;
        }
        __syncthreads();
    }
    for (int c0 = 0; c0 < deg; c0 += CH2) {
        int n = min(CH2, deg - c0);
        if (tid < n) {
            int s_ = srcs[base + c0 + tid];
            float l = als[s_] + aldi;
            l = l > 0.f ? l : 0.2f * l;
            w[tid] = expf(l - sm);
        }
        __syncthreads();
        if (tid == 0) {
            float s = ss;
            for (int e = 0; e < n; e++) s += w[e];
            ss = s;
        }
        __syncthreads();
    }
    if (tid == 0) sinv = 1.f / (ss + 1e-16f);
    __syncthreads();
    float acc = 0.f;
    for (int c0 = 0; c0 < deg; c0 += CH2) {
        int n = min(CH2, deg - c0);
        if (tid < n) {
            int s_ = srcs[base + c0 + tid];
            ssrc[tid] = s_;
            float l = als[s_] + aldi;
            l = l > 0.f ? l : 0.2f * l;
            w[tid] = expf(l - sm) * sinv;
        }
        __syncthreads();
        for (int e = 0; e < n; e++)
            acc += w[e] * h2[(long)ssrc[e] * C2 + tid];
        __syncthreads();
    }
    float v = acc + b2[tid];
    out[(long)i * C2 + tid] = fmaxf(v, 0.f);
}

// ---------------- pooling ----------------
__global__ void starts_k(const int* __restrict__ batch, int* starts) {
    int i = blockIdx.x * blockDim.x + threadIdx.x;
    if (i >= N_NODES) return;
    if (i == 0) starts[0] = 0;
    else if (batch[i] != batch[i - 1]) starts[batch[i]] = i;
    if (i == N_NODES - 1) starts[BATCH] = N_NODES;
}
__global__ void pool_k(const float* __restrict__ o2, const int* __restrict__ starts,
                       float* __restrict__ g) {
    int b = blockIdx.x, c = threadIdx.x;  // 128 threads
    int s = starts[b], e = starts[b + 1];
    float m = -1e30f;
    for (int r = s; r < e; r++) m = fmaxf(m, o2[(long)r * C2 + c]);
    g[b * C2 + c] = m;
}

// ---------------- conv branch: scatter conv_w by token-id ----------------
__global__ void scatterA_k(const int* __restrict__ target, const float* __restrict__ cw,
                           float* __restrict__ A) {
    int b = blockIdx.x, tid = threadIdx.x;  // 256 threads = (o,k)
    __shared__ float Ash[NF * VOCAB * KW];
    for (int i = tid; i < NF * VOCAB * KW; i += 256) Ash[i] = 0.f;
    __syncthreads();
    int o = tid >> 3, k = tid & 7;
    const float* wrow = cw + o * (SEQ * KW) + k;
    float* arow = Ash + o * (VOCAB * KW) + k;
    for (int s = 0; s < SEQ; s++) {
        int v = target[b * SEQ + s];
        arow[v * KW] += wrow[s * KW];
    }
    __syncthreads();
    for (int i = tid; i < NF * VOCAB * KW; i += 256)
        A[(long)b * (NF * VOCAB * KW) + i] = Ash[i];
}
__global__ void ek_k(const float* __restrict__ emb, float* __restrict__ Ek) {
    int idx = blockIdx.x * blockDim.x + threadIdx.x;
    if (idx >= VOCAB * KW * LOUT) return;
    int vk = idx / LOUT, l = idx - vk * LOUT;
    Ek[idx] = emb[(vk >> 3) * EMBD + (vk & 7) + l];
}
__global__ void conv_epi_k(float* __restrict__ c, const float* __restrict__ cb) {
    int idx = blockIdx.x * blockDim.x + threadIdx.x;
    if (idx >= BATCH * NF * LOUT) return;
    int o = (idx / LOUT) & (NF - 1);
    c[idx] = fmaxf(c[idx] + cb[o], 0.f);
}

// ---------------- final ----------------
__global__ void final_k(const float* __restrict__ x, const float* __restrict__ w,
                        const float* __restrict__ b, float* __restrict__ y) {
    int gw = (blockIdx.x * blockDim.x + threadIdx.x) >> 5;
    int lane = threadIdx.x & 31;
    if (gw >= BATCH) return;
    float s = 0.f;
#pragma unroll
    for (int j = lane; j < 256; j += 32) s += x[gw * 256 + j] * w[j];
#pragma unroll
    for (int o = 16; o; o >>= 1) s += __shfl_down_sync(0xffffffffu, s, o);
    if (lane == 0) y[gw] = s + b[0];
}

// ---------------- host ----------------
extern "C" void kernel_launch(void* const* d_in, const int* in_sizes, int n_in,
                              void* d_out, int out_size) {
    const float* x       = (const float*)d_in[0];
    const int*   ei      = (const int*)d_in[1];
    const int*   batch   = (const int*)d_in[2];
    const int*   target  = (const int*)d_in[3];
    const float* W1      = (const float*)d_in[4];
    const float* a_src1  = (const float*)d_in[5];
    const float* a_dst1  = (const float*)d_in[6];
    const float* b1      = (const float*)d_in[7];
    const float* W2      = (const float*)d_in[8];
    const float* a_src2  = (const float*)d_in[9];
    const float* a_dst2  = (const float*)d_in[10];
    const float* b2      = (const float*)d_in[11];
    const float* fc_g1_w = (const float*)d_in[12];
    const float* fc_g1_b = (const float*)d_in[13];
    const float* emb     = (const float*)d_in[14];
    const float* conv_w  = (const float*)d_in[15];
    const float* conv_b  = (const float*)d_in[16];
    const float* fc_xt_w = (const float*)d_in[17];
    const float* fc_xt_b = (const float*)d_in[18];
    const float* fc1_w   = (const float*)d_in[19];
    const float* fc1_b   = (const float*)d_in[20];
    const float* fc2_w   = (const float*)d_in[21];
    const float* fc2_b   = (const float*)d_in[22];
    const float* out_w   = (const float*)d_in[23];
    const float* out_b   = (const float*)d_in[24];
    float* y = (float*)d_out;
    int E = in_sizes[1] / 2;

    float *h1p, *h1ep, *h2p, *o2p, *als1p, *ald1p, *als2p, *ald2p;
    float *Ap, *Ekp, *convp, *poolp, *xcp, *f1p, *f2p;
    int *degp, *offp, *curp, *srcsp, *startsp;
    cudaGetSymbolAddress((void**)&h1p, g_h1);
    cudaGetSymbolAddress((void**)&h1ep, g_h1e);
    cudaGetSymbolAddress((void**)&h2p, g_h2);
    cudaGetSymbolAddress((void**)&o2p, g_o2);
    cudaGetSymbolAddress((void**)&als1p, g_als1);
    cudaGetSymbolAddress((void**)&ald1p, g_ald1);
    cudaGetSymbolAddress((void**)&als2p, g_als2);
    cudaGetSymbolAddress((void**)&ald2p, g_ald2);
    cudaGetSymbolAddress((void**)&degp, g_deg);
    cudaGetSymbolAddress((void**)&offp, g_off);
    cudaGetSymbolAddress((void**)&curp, g_cur);
    cudaGetSymbolAddress((void**)&srcsp, g_srcs);
    cudaGetSymbolAddress((void**)&startsp, g_starts);
    cudaGetSymbolAddress((void**)&Ap, g_A);
    cudaGetSymbolAddress((void**)&Ekp, g_Ek);
    cudaGetSymbolAddress((void**)&convp, g_conv);
    cudaGetSymbolAddress((void**)&poolp, g_pool);
    cudaGetSymbolAddress((void**)&xcp, g_xc);
    cudaGetSymbolAddress((void**)&f1p, g_f1);
    cudaGetSymbolAddress((void**)&f2p, g_f2);

    // CSR build
    deg_init_k<<<(N_NODES + 255) / 256, 256>>>(degp);
    hist_k<<<(E + 255) / 256, 256>>>(ei, degp, E);
    scan_k<<<1, 1024>>>(degp, offp, N_NODES);
    selfloop_k<<<(N_NODES + 255) / 256, 256>>>(offp, curp, srcsp);
    fill_k<<<(E + 255) / 256, 256>>>(ei, curp, srcsp, E);

    // GAT layer 1: h1 = x @ W1  [50000,78]@[78,780]
    {
        dim3 g((D1 + 63) / 64, (N_NODES + 127) / 128);
        gemm_tf32_k<false, false, false><<<g, 256>>>(N_NODES, D1, F0, x, F0, W1, D1, h1p, D1, nullptr, F0);
    }
    attn1_k<<<(N_NODES * NH1 + 255) / 256, 256>>>(h1p, a_src1, a_dst1, als1p, ald1p);
    agg1_k<<<N_NODES, 256>>>(h1p, als1p, ald1p, offp, srcsp, b1, h1ep);

    // GAT layer 2: h2 = h1e @ W2  [50000,780]@[780,128]
    {
        dim3 g((C2 + 63) / 64, (N_NODES + 127) / 128);
        gemm_tf32_k<false, false, false><<<g, 256>>>(N_NODES, C2, D1, h1ep, D1, W2, C2, h2p, C2, nullptr, D1);
    }
    attn2_k<<<(N_NODES + 255) / 256, 256>>>(h2p, a_src2, a_dst2, als2p, ald2p);
    agg2_k<<<N_NODES, 128>>>(h2p, als2p, ald2p, offp, srcsp, b2, o2p);

    // pooling + fc_g1 -> xc[:, :128]
    starts_k<<<(N_NODES + 255) / 256, 256>>>(batch, startsp);
    pool_k<<<BATCH, C2>>>(o2p, startsp, poolp);
    bias_init_k<<<(BATCH * C2 + 255) / 256, 256>>>(xcp, 2 * C2, BATCH, C2, fc_g1_b);
    {
        dim3 g(2, 4, 4);
        gemm_tf32_k<false, false, true><<<g, 256>>>(BATCH, C2, C2, poolp, C2, fc_g1_w, C2, xcp, 2 * C2, nullptr, 32);
    }
    relu_ip_k<<<(BATCH * C2 + 255) / 256, 256>>>(xcp, 2 * C2, BATCH, C2);

    // conv branch -> xc[:, 128:]
    scatterA_k<<<BATCH, 256>>>(target, conv_w, Ap);
    ek_k<<<(VOCAB * KW * LOUT + 255) / 256, 256>>>(emb, Ekp);
    {
        dim3 g((LOUT + 63) / 64, (BATCH * NF + 127) / 128);
        gemm_tf32_k<false, false, false><<<g, 256>>>(BATCH * NF, LOUT, VOCAB * KW, Ap, VOCAB * KW, Ekp, LOUT,
                                                     convp, LOUT, nullptr, VOCAB * KW);
    }
    conv_epi_k<<<(BATCH * NF * LOUT + 255) / 256, 256>>>(convp, conv_b);
    bias_init_k<<<(BATCH * C2 + 255) / 256, 256>>>(xcp + C2, 2 * C2, BATCH, C2, fc_xt_b);
    {
        dim3 g(2, 4, 8);
        gemm_tf32_k<false, false, true><<<g, 256>>>(BATCH, C2, NF * LOUT, convp, NF * LOUT, fc_xt_w, C2,
                                                    xcp + C2, 2 * C2, nullptr, 484);
    }

    // MLP head
    {
        dim3 g(16, 4);
        gemm_tf32_k<true, true, false><<<g, 256>>>(BATCH, 1024, 256, xcp, 256, fc1_w, 1024, f1p, 1024, fc1_b, 256);
    }
    bias_init_k<<<(BATCH * 256 + 255) / 256, 256>>>(f2p, 256, BATCH, 256, fc2_b);
    {
        dim3 g(4, 4, 4);
        gemm_tf32_k<false, false, true><<<g, 256>>>(BATCH, 256, 1024, f1p, 1024, fc2_w, 256, f2p, 256, nullptr, 256);
    }
    relu_ip_k<<<(BATCH * 256 + 255) / 256, 256>>>(f2p, 256, BATCH, 256);
    final_k<<<64, 256>>>(f2p, out_w, out_b, y);
}